// round 1
// baseline (speedup 1.0000x reference)
#include <cuda_runtime.h>
#include <cuda_bf16.h>
#include <math.h>

#define BN 4
#define HH 192
#define WW 192
#define PP (HH*WW)           // 36864
#define CF 64
#define ONC 64
#define INC 7

// ---------------- scratch (device globals; no runtime allocation) ----------------
__device__ float g_dw[BN * CF * PP];            // depthwise output        37.7 MB
__device__ float g_om[BN * 525 * PP];           // offset/mask (max k=5)  309.7 MB
__device__ float g_stack[BN * 3 * ONC * PP];    // stacked branch outputs 113.2 MB
__device__ float g_attfull[BN * ONC * PP];      // attn pre-mean           37.7 MB
__device__ float g_att[BN * ONC];
__device__ float g_atts[BN * 3 * ONC];
__device__ float g_Wb[BN * ONC * 3 * ONC];      // per-batch scaled conv_w

// ---------------- depthwise conv (k = 1,3,5, SAME padding) ----------------
template <int KK>
__global__ void dw_conv_kernel(const float* __restrict__ x,
                               const float* __restrict__ w,
                               const float* __restrict__ bias,
                               float* __restrict__ y)
{
    int idx = blockIdx.x * blockDim.x + threadIdx.x;
    const int total = BN * CF * PP;
    if (idx >= total) return;
    int px = idx % WW;
    int h  = (idx / WW) % HH;
    int c  = (idx / PP) % CF;
    int b  = idx / (CF * PP);
    const int pad = KK / 2;
    const float* xp = x + ((long)(b * CF + c)) * PP;
    const float* wp = w + c * KK * KK;
    float acc = bias[c];
#pragma unroll
    for (int ky = 0; ky < KK; ky++) {
#pragma unroll
        for (int kx = 0; kx < KK; kx++) {
            int yy = h + ky - pad;
            int xx = px + kx - pad;
            if (yy >= 0 && yy < HH && xx >= 0 && xx < WW)
                acc += xp[yy * WW + xx] * wp[ky * KK + kx];
        }
    }
    y[idx] = acc;
}

// ---------------- pointwise GEMM: Y[b,oc,p] = sum_c W[oc,c]*X[b,c,p] + bias ----------------
// tile: 64 pixels x 64 oc, 16x16 threads, 4x4 micro-tile
__global__ void pw_gemm_kernel(const float* __restrict__ X,
                               const float* __restrict__ W,
                               const float* __restrict__ bias,
                               float* __restrict__ Y,
                               int C, int OC, int P,
                               long xbs, long ybs, long wbs, int relu)
{
    __shared__ float Xs[16][64];
    __shared__ float Ws[64][17];

    int b = blockIdx.z;
    const float* Xb = X + (long)b * xbs;
    const float* Wp = W + (long)b * wbs;
    float*       Yb = Y + (long)b * ybs;

    int p0  = blockIdx.x * 64;
    int oc0 = blockIdx.y * 64;
    int tx = threadIdx.x, ty = threadIdx.y;
    int t = ty * 16 + tx;

    float acc[4][4] = {};

    for (int c0 = 0; c0 < C; c0 += 16) {
        for (int i = t; i < 16 * 64; i += 256) {
            int cc = i >> 6, pp = i & 63;
            Xs[cc][pp] = Xb[(long)(c0 + cc) * P + p0 + pp];
        }
        for (int i = t; i < 64 * 16; i += 256) {
            int oo = i >> 4, cc = i & 15;
            int oc = oc0 + oo;
            Ws[oo][cc] = (oc < OC) ? Wp[(long)oc * C + c0 + cc] : 0.f;
        }
        __syncthreads();
#pragma unroll
        for (int cc = 0; cc < 16; cc++) {
            float xv[4], wv[4];
#pragma unroll
            for (int i = 0; i < 4; i++) xv[i] = Xs[cc][tx + 16 * i];
#pragma unroll
            for (int j = 0; j < 4; j++) wv[j] = Ws[ty + 16 * j][cc];
#pragma unroll
            for (int j = 0; j < 4; j++)
#pragma unroll
                for (int i = 0; i < 4; i++)
                    acc[i][j] += xv[i] * wv[j];
        }
        __syncthreads();
    }

#pragma unroll
    for (int j = 0; j < 4; j++) {
        int oc = oc0 + ty + 16 * j;
        if (oc < OC) {
            float bb = bias[oc];
#pragma unroll
            for (int i = 0; i < 4; i++) {
                float v = acc[i][j] + bb;
                if (relu) v = fmaxf(v, 0.f);
                Yb[(long)oc * P + p0 + tx + 16 * i] = v;
            }
        }
    }
}

// ---------------- modulated deformable conv ----------------
// x: [B,7,H,W], om: [B, 21*K, P] (offsets: 2*(c*K+kk), +1; mask raw at 14K + c*K+kk)
// w: [64, 7, K], out written to g_stack[b, branch, o, p], with relu(+bias)
template <int KK>
__global__ void mdcn_kernel(const float* __restrict__ xin,
                            const float* __restrict__ om,
                            const float* __restrict__ w,
                            const float* __restrict__ bias,
                            float* __restrict__ out,
                            int branch)
{
    constexpr int K  = KK * KK;
    constexpr int CK = INC * K;
    __shared__ float Ws[CK][64];       // [c*K+kk][o], rows 256B-aligned

    int tid = threadIdx.x;
    for (int i = tid; i < CK * 64; i += blockDim.x) {
        int ck = i >> 6, o = i & 63;
        Ws[ck][o] = w[o * CK + ck];
    }
    __syncthreads();

    int p = blockIdx.x * blockDim.x + tid;
    int b = blockIdx.y;
    if (p >= PP) return;
    int h  = p / WW;
    int wx = p - h * WW;
    const int pad = KK / 2;

    const float* omb = om + (long)b * (3 * CK) * PP;
    const float* xb  = xin + (long)b * INC * PP;

    float acc[64];
#pragma unroll
    for (int o = 0; o < 64; o++) acc[o] = 0.f;

    for (int c = 0; c < INC; c++) {
        const float* xc = xb + c * PP;
#pragma unroll
        for (int kk = 0; kk < K; kk++) {
            int ck = c * K + kk;
            float oy   = omb[(long)(2 * ck + 0) * PP + p];
            float ox   = omb[(long)(2 * ck + 1) * PP + p];
            float mraw = omb[(long)(2 * CK + ck) * PP + p];
            float m = 1.f / (1.f + expf(-mraw));

            float py = oy + (float)(kk / KK) + (float)h - (float)pad;
            float px = ox + (float)(kk % KK) + (float)wx - (float)pad;
            float fy0 = floorf(py), fx0 = floorf(px);
            float wy = py - fy0, wxx = px - fx0;
            int iy0 = (int)fy0, ix0 = (int)fx0;
            int iy1 = iy0 + 1, ix1 = ix0 + 1;

            bool vy0 = (iy0 >= 0) & (iy0 < HH);
            bool vy1 = (iy1 >= 0) & (iy1 < HH);
            bool vx0 = (ix0 >= 0) & (ix0 < WW);
            bool vx1 = (ix1 >= 0) & (ix1 < WW);
            int cy0 = min(max(iy0, 0), HH - 1);
            int cy1 = min(max(iy1, 0), HH - 1);
            int cx0 = min(max(ix0, 0), WW - 1);
            int cx1 = min(max(ix1, 0), WW - 1);

            float v00 = (vy0 & vx0) ? xc[cy0 * WW + cx0] : 0.f;
            float v01 = (vy0 & vx1) ? xc[cy0 * WW + cx1] : 0.f;
            float v10 = (vy1 & vx0) ? xc[cy1 * WW + cx0] : 0.f;
            float v11 = (vy1 & vx1) ? xc[cy1 * WW + cx1] : 0.f;

            float s = (v00 * (1.f - wy) * (1.f - wxx) +
                       v01 * (1.f - wy) * wxx +
                       v10 * wy * (1.f - wxx) +
                       v11 * wy * wxx) * m;

            const float4* wr = reinterpret_cast<const float4*>(&Ws[ck][0]);
#pragma unroll
            for (int j = 0; j < 16; j++) {
                float4 w4 = wr[j];
                acc[4 * j + 0] += s * w4.x;
                acc[4 * j + 1] += s * w4.y;
                acc[4 * j + 2] += s * w4.z;
                acc[4 * j + 3] += s * w4.w;
            }
        }
    }

    float* ob = out + ((long)(b * 3 + branch) * 64) * PP + p;
#pragma unroll
    for (int o = 0; o < 64; o++)
        ob[(long)o * PP] = fmaxf(acc[o] + bias[o], 0.f);
}

// ---------------- mean over pixels: att[b,o] = mean_p attfull[b,o,p] ----------------
__global__ void mean_reduce_kernel(const float* __restrict__ in, float* __restrict__ out)
{
    int o = blockIdx.x, b = blockIdx.y;
    const float* ptr = in + ((long)b * 64 + o) * PP;
    float s = 0.f;
    for (int i = threadIdx.x; i < PP; i += 256) s += ptr[i];
    __shared__ float sm[256];
    sm[threadIdx.x] = s;
    __syncthreads();
    for (int st = 128; st > 0; st >>= 1) {
        if (threadIdx.x < st) sm[threadIdx.x] += sm[threadIdx.x + st];
        __syncthreads();
    }
    if (threadIdx.x == 0) out[b * 64 + o] = sm[0] / (float)PP;
}

// ---------------- tiny head: fc -> relu -> fcs -> atts; fold atts into conv_w ----------------
__global__ void head_kernel(const float* __restrict__ att,
                            const float* __restrict__ fc_w, const float* __restrict__ fc_b,
                            const float* __restrict__ fw0, const float* __restrict__ fb0,
                            const float* __restrict__ fw1, const float* __restrict__ fb1,
                            const float* __restrict__ fw2, const float* __restrict__ fb2,
                            const float* __restrict__ conv_w,
                            float* __restrict__ Wb, float* __restrict__ atts)
{
    __shared__ float a2[BN][32];
    int t = threadIdx.x;
    if (t < BN * 32) {
        int b = t >> 5, o = t & 31;
        float s = fc_b[o];
        for (int c = 0; c < 64; c++) s += fc_w[o * 64 + c] * att[b * 64 + c];
        a2[b][o] = fmaxf(s, 0.f);
    }
    __syncthreads();
    __shared__ float as[BN][192];
    for (int idx = t; idx < BN * 192; idx += blockDim.x) {
        int b = idx / 192, r = idx % 192;
        int i = r / 64, o = r % 64;
        const float* fw = (i == 0) ? fw0 : ((i == 1) ? fw1 : fw2);
        const float* fb = (i == 0) ? fb0 : ((i == 1) ? fb1 : fb2);
        float s = fb[o];
        for (int c = 0; c < 32; c++) s += fw[o * 32 + c] * a2[b][c];
        as[b][r] = s;
        atts[idx] = s;
    }
    __syncthreads();
    for (int idx = t; idx < BN * 64 * 192; idx += blockDim.x) {
        int b  = idx / (64 * 192);
        int r  = idx % (64 * 192);
        int o  = r / 192;
        int tc = r % 192;
        Wb[idx] = conv_w[o * 192 + tc] * as[b][tc];
    }
}

// ---------------- launch ----------------
extern "C" void kernel_launch(void* const* d_in, const int* in_sizes, int n_in,
                              void* d_out, int out_size)
{
    (void)in_sizes; (void)n_in; (void)out_size;
    const float* fea    = (const float*)d_in[0];
    const float* inputs = (const float*)d_in[1];
    const float* attn_w = (const float*)d_in[20];
    const float* attn_b = (const float*)d_in[21];
    const float* fc_w   = (const float*)d_in[22];
    const float* fc_b   = (const float*)d_in[23];
    const float* conv_w = (const float*)d_in[30];
    const float* conv_b = (const float*)d_in[31];

    float *dw, *om, *stack, *attfull, *att, *atts, *Wb;
    cudaGetSymbolAddress((void**)&dw, g_dw);
    cudaGetSymbolAddress((void**)&om, g_om);
    cudaGetSymbolAddress((void**)&stack, g_stack);
    cudaGetSymbolAddress((void**)&attfull, g_attfull);
    cudaGetSymbolAddress((void**)&att, g_att);
    cudaGetSymbolAddress((void**)&atts, g_atts);
    cudaGetSymbolAddress((void**)&Wb, g_Wb);

    const int P = PP;
    dim3 gthr(16, 16);

    for (int i = 0; i < 3; i++) {
        const float* dww  = (const float*)d_in[2 + 6 * i];
        const float* dwb  = (const float*)d_in[3 + 6 * i];
        const float* pww  = (const float*)d_in[4 + 6 * i];
        const float* pwb  = (const float*)d_in[5 + 6 * i];
        const float* dcnw = (const float*)d_in[6 + 6 * i];
        const float* dcnb = (const float*)d_in[7 + 6 * i];
        int k  = 2 * i + 1;
        int oc = INC * 3 * k * k;   // 21, 189, 525

        int total = BN * CF * PP;
        int blocks = (total + 255) / 256;
        if (i == 0) dw_conv_kernel<1><<<blocks, 256>>>(fea, dww, dwb, dw);
        if (i == 1) dw_conv_kernel<3><<<blocks, 256>>>(fea, dww, dwb, dw);
        if (i == 2) dw_conv_kernel<5><<<blocks, 256>>>(fea, dww, dwb, dw);

        dim3 ggrid(P / 64, (oc + 63) / 64, BN);
        pw_gemm_kernel<<<ggrid, gthr>>>(dw, pww, pwb, om,
                                        64, oc, P,
                                        (long)64 * P, (long)oc * P, 0, 0);

        dim3 mgrid(PP / 128, BN);
        if (i == 0) mdcn_kernel<1><<<mgrid, 128>>>(inputs, om, dcnw, dcnb, stack, i);
        if (i == 1) mdcn_kernel<3><<<mgrid, 128>>>(inputs, om, dcnw, dcnb, stack, i);
        if (i == 2) mdcn_kernel<5><<<mgrid, 128>>>(inputs, om, dcnw, dcnb, stack, i);
    }

    // attention: relu(pw(stack, attn_w)) -> mean
    dim3 agrid(P / 64, 1, BN);
    pw_gemm_kernel<<<agrid, gthr>>>(stack, attn_w, attn_b, attfull,
                                    192, 64, P,
                                    (long)192 * P, (long)64 * P, 0, 1);
    dim3 rgrid(64, BN);
    mean_reduce_kernel<<<rgrid, 256>>>(attfull, att);

    head_kernel<<<1, 256>>>(att, fc_w, fc_b,
                            (const float*)d_in[24], (const float*)d_in[25],
                            (const float*)d_in[26], (const float*)d_in[27],
                            (const float*)d_in[28], (const float*)d_in[29],
                            conv_w, Wb, atts);

    // final: relu(pw(stack * atts, conv_w)) with atts folded into per-batch weights
    pw_gemm_kernel<<<agrid, gthr>>>(stack, Wb, conv_b, (float*)d_out,
                                    192, 64, P,
                                    (long)192 * P, (long)64 * P, (long)64 * 192, 1);
}